// round 14
// baseline (speedup 1.0000x reference)
#include <cuda_runtime.h>
#include <cuda_fp16.h>
#include <cstdint>
#include <math.h>

#define BB 4
#define SS 2048
#define DD 768
#define UU 768
#define UQKV (3 * UU)        // 2304

// ---------------- scratch (static __device__; allocs forbidden) --------------
__device__ __half g_Xh[BB * SS * DD];
__device__ __half g_QKV[(size_t)BB * SS * UQKV];   // packed [B*S, 3U]: Q | K | V
__device__ __half g_Vth[BB * UU * SS];
__device__ __half g_Wall[UQKV * DD];               // [3U, D]
__device__ float  g_Sc[(size_t)BB * SS * SS];
__device__ __half g_P[(size_t)BB * SS * SS];

// ---------------- helpers ----------------------------------------------------
__device__ __forceinline__ void cp16(uint32_t s, const void* g) {
    asm volatile("cp.async.cg.shared.global [%0], [%1], 16;\n" :: "r"(s), "l"(g) : "memory");
}
__device__ __forceinline__ void cp_commit() {
    asm volatile("cp.async.commit_group;\n" ::: "memory");
}
template <int N>
__device__ __forceinline__ void cp_wait() {
    asm volatile("cp.async.wait_group %0;\n" :: "n"(N) : "memory");
}
__device__ __forceinline__ void mma_f16(float* d, const uint32_t* a, const uint32_t* b) {
    asm volatile("mma.sync.aligned.m16n8k16.row.col.f32.f16.f16.f32 "
                 "{%0,%1,%2,%3}, {%4,%5,%6,%7}, {%8,%9}, {%0,%1,%2,%3};"
                 : "+f"(d[0]), "+f"(d[1]), "+f"(d[2]), "+f"(d[3])
                 : "r"(a[0]), "r"(a[1]), "r"(a[2]), "r"(a[3]), "r"(b[0]), "r"(b[1]));
}
__device__ __forceinline__ void ldsm4(uint32_t& r0, uint32_t& r1, uint32_t& r2, uint32_t& r3,
                                      uint32_t addr) {
    asm volatile("ldmatrix.sync.aligned.m8n8.x4.shared.b16 {%0,%1,%2,%3}, [%4];"
                 : "=r"(r0), "=r"(r1), "=r"(r2), "=r"(r3) : "r"(addr));
}

// ---------------- fp16 warp-MMA GEMM: C = alpha * A * B^T --------------------
// Template MT = CTA M-tile (128 or 64). N-tile fixed 128. 8 warps.
// MT=128: warp tile 64x32 (MI=4). MT=64: warp tile 32x32 (MI=2).
// K-chunk 64 halves, 3-stage cp.async pipeline, ONE barrier per chunk.
#define STRDH 72

template <int MT, bool HALF_OUT>
__global__ __launch_bounds__(256, 2) void gemm_h(
    const __half* __restrict__ A, const __half* __restrict__ B, void* __restrict__ Cv,
    int K, int ldA, int ldB, int ldC,
    long sA, long sB, long sC, float alpha)
{
    constexpr int MI = MT / 32;                  // m16 tiles per warp
    constexpr int TILE_A = MT * STRDH;           // halves per A stage
    constexpr int TILE_B = 128 * STRDH;          // halves per B stage

    extern __shared__ __half sm[];
    A += (long)blockIdx.z * sA;
    B += (long)blockIdx.z * sB;

    const int row0 = blockIdx.y * MT;
    const int col0 = blockIdx.x * 128;
    const int tid  = threadIdx.x;
    const int wid  = tid >> 5;
    const int lane = tid & 31;
    const int g    = lane >> 2;
    const int t    = lane & 3;
    const int wm   = wid & 1;
    const int wn   = wid >> 1;

    const uint32_t sA0 = (uint32_t)__cvta_generic_to_shared(sm);
    const uint32_t sB0 = (uint32_t)__cvta_generic_to_shared(sm + 3 * TILE_A);

    const int aRow = wm * (MT / 2) + (lane & 15);
    const int aK8  = (lane >> 4) * 8;
    const int bRow = wn * 32 + ((lane >> 4) << 3) + (lane & 7);
    const int bK8  = ((lane >> 3) & 1) * 8;

    float acc[MI][4][4];
#pragma unroll
    for (int i = 0; i < MI; i++)
#pragma unroll
        for (int j = 0; j < 4; j++)
#pragma unroll
            for (int r = 0; r < 4; r++) acc[i][j][r] = 0.f;

    const int KT = K / 64;

    auto load_tile = [&](int buf, int k0) {
        const uint32_t dA = sA0 + (uint32_t)(buf * TILE_A * 2);
        const uint32_t dB = sB0 + (uint32_t)(buf * TILE_B * 2);
#pragma unroll
        for (int i = 0; i < MT / 32; i++) {      // A: MT rows x 8 chunks
            int idx = tid + i * 256;
            int r   = idx >> 3;
            int c   = idx & 7;
            cp16(dA + (uint32_t)((r * STRDH + c * 8) * 2), A + (long)(row0 + r) * ldA + k0 + c * 8);
        }
#pragma unroll
        for (int i = 0; i < 4; i++) {            // B: 128 rows x 8 chunks
            int idx = tid + i * 256;
            int r   = idx >> 3;
            int c   = idx & 7;
            cp16(dB + (uint32_t)((r * STRDH + c * 8) * 2), B + (long)(col0 + r) * ldB + k0 + c * 8);
        }
        cp_commit();
    };

    load_tile(0, 0);
    load_tile(1, 64);

    int buf = 0;
    for (int kt = 0; kt < KT; kt++) {
        if (kt + 1 < KT) cp_wait<1>(); else cp_wait<0>();
        __syncthreads();
        if (kt + 2 < KT) {
            int wbuf = buf + 2; if (wbuf >= 3) wbuf -= 3;
            load_tile(wbuf, (kt + 2) * 64);
        }

        const uint32_t abase = sA0 + (uint32_t)(buf * TILE_A * 2);
        const uint32_t bbase = sB0 + (uint32_t)(buf * TILE_B * 2);

#pragma unroll
        for (int ks = 0; ks < 4; ks++) {
            const int kb = ks * 16;
            uint32_t af[MI][4], bf[4][2];
#pragma unroll
            for (int mi = 0; mi < MI; mi++) {
                uint32_t addr = abase + (uint32_t)(((aRow + mi * 16) * STRDH + kb + aK8) * 2);
                ldsm4(af[mi][0], af[mi][1], af[mi][2], af[mi][3], addr);
            }
#pragma unroll
            for (int j = 0; j < 2; j++) {
                uint32_t addr = bbase + (uint32_t)(((bRow + j * 16) * STRDH + kb + bK8) * 2);
                ldsm4(bf[2 * j][0], bf[2 * j][1], bf[2 * j + 1][0], bf[2 * j + 1][1], addr);
            }
#pragma unroll
            for (int mi = 0; mi < MI; mi++)
#pragma unroll
                for (int ni = 0; ni < 4; ni++)
                    mma_f16(acc[mi][ni], af[mi], bf[ni]);
        }
        buf++; if (buf == 3) buf = 0;
    }

    // epilogue
#pragma unroll
    for (int mi = 0; mi < MI; mi++) {
        const int r0 = row0 + wm * (MT / 2) + mi * 16 + g;
#pragma unroll
        for (int ni = 0; ni < 4; ni++) {
            const int c = col0 + wn * 32 + ni * 8 + 2 * t;
            float v0 = acc[mi][ni][0] * alpha, v1 = acc[mi][ni][1] * alpha;
            float v2 = acc[mi][ni][2] * alpha, v3 = acc[mi][ni][3] * alpha;
            if (HALF_OUT) {
                __half* C = (__half*)Cv + (long)blockIdx.z * sC;
                *(__half2*)(C + (long)r0 * ldC + c)       = __floats2half2_rn(v0, v1);
                *(__half2*)(C + (long)(r0 + 8) * ldC + c) = __floats2half2_rn(v2, v3);
            } else {
                float* C = (float*)Cv + (long)blockIdx.z * sC;
                *(float2*)(C + (long)r0 * ldC + c)       = make_float2(v0, v1);
                *(float2*)(C + (long)(r0 + 8) * ldC + c) = make_float2(v2, v3);
            }
        }
    }
}

#define SMEM_128 (3 * (128 + 128) * STRDH * 2)   // 110592
#define SMEM_64  (3 * (64 + 128) * STRDH * 2)    // 82944

// ---------------- fp32 -> fp16 copy ------------------------------------------
__global__ __launch_bounds__(256) void cvt_half(const float* __restrict__ in,
                                                __half* __restrict__ out, int n4)
{
    int i = blockIdx.x * 256 + threadIdx.x;
    if (i < n4) {
        float4 v = ((const float4*)in)[i];
        ((__half2*)out)[2 * i]     = __floats2half2_rn(v.x, v.y);
        ((__half2*)out)[2 * i + 1] = __floats2half2_rn(v.z, v.w);
    }
}

// ---------------- transpose float->half --------------------------------------
__global__ __launch_bounds__(256) void transpose_f2h(
    const float* __restrict__ in, __half* __restrict__ out, int R, int C)
{
    __shared__ float tbuf[32][33];
    const int c0 = blockIdx.x * 32, r0 = blockIdx.y * 32;
    const int tx = threadIdx.x & 31, ty = threadIdx.x >> 5;
#pragma unroll
    for (int i = 0; i < 32; i += 8)
        tbuf[ty + i][tx] = in[(long)(r0 + ty + i) * C + c0 + tx];
    __syncthreads();
#pragma unroll
    for (int i = 0; i < 32; i += 8)
        out[(long)(c0 + ty + i) * R + r0 + tx] = __float2half_rn(tbuf[tx][ty + i]);
}

// ---------------- transpose half->half with strides --------------------------
__global__ __launch_bounds__(256) void transpose_h(
    const __half* __restrict__ in, __half* __restrict__ out,
    int ldIn, int ldOut, long sIn, long sOut)
{
    __shared__ float tbuf[32][33];
    in  += (long)blockIdx.z * sIn;
    out += (long)blockIdx.z * sOut;
    const int c0 = blockIdx.x * 32, r0 = blockIdx.y * 32;
    const int tx = threadIdx.x & 31, ty = threadIdx.x >> 5;
#pragma unroll
    for (int i = 0; i < 32; i += 8)
        tbuf[ty + i][tx] = __half2float(in[(long)(r0 + ty + i) * ldIn + c0 + tx]);
    __syncthreads();
#pragma unroll
    for (int i = 0; i < 32; i += 8)
        out[(long)(c0 + ty + i) * ldOut + r0 + tx] = __float2half_rn(tbuf[tx][ty + i]);
}

// ---------------- row softmax over S=2048: float in, half out ----------------
__global__ __launch_bounds__(256) void softmax_rows(const float* __restrict__ scores,
                                                    __half* __restrict__ P)
{
    const float* row = scores + (long)blockIdx.x * SS;
    __half* prow = P + (long)blockIdx.x * SS;
    __shared__ float red[8];
    __shared__ float red2[8];
    const int t = threadIdx.x;
    const int lane = t & 31, warp = t >> 5;

    float v[8];
    float m = -INFINITY;
#pragma unroll
    for (int i = 0; i < 8; i++) { v[i] = row[t + i * 256]; m = fmaxf(m, v[i]); }
#pragma unroll
    for (int off = 16; off > 0; off >>= 1)
        m = fmaxf(m, __shfl_xor_sync(0xFFFFFFFFu, m, off));
    if (lane == 0) red[warp] = m;
    __syncthreads();
#pragma unroll
    for (int w = 0; w < 8; w++) m = fmaxf(m, red[w]);

    float sum = 0.f;
#pragma unroll
    for (int i = 0; i < 8; i++) { v[i] = __expf(v[i] - m); sum += v[i]; }
#pragma unroll
    for (int off = 16; off > 0; off >>= 1)
        sum += __shfl_xor_sync(0xFFFFFFFFu, sum, off);
    if (lane == 0) red2[warp] = sum;
    __syncthreads();
    sum = 0.f;
#pragma unroll
    for (int w = 0; w < 8; w++) sum += red2[w];

    float inv = 1.f / sum;
#pragma unroll
    for (int i = 0; i < 8; i++) prow[t + i * 256] = __float2half_rn(v[i] * inv);
}

// ---------------------------------------------------------------------------
extern "C" void kernel_launch(void* const* d_in, const int* in_sizes, int n_in,
                              void* d_out, int out_size)
{
    (void)in_sizes; (void)n_in; (void)out_size;
    const float* x  = (const float*)d_in[0];
    const float* Wq = (const float*)d_in[1];
    const float* Wk = (const float*)d_in[2];
    const float* Wv = (const float*)d_in[3];
    float* out = (float*)d_out;

    __half *Xh, *QKV, *Vth, *Wall, *P;
    float *Sc;
    cudaGetSymbolAddress((void**)&Xh,   g_Xh);
    cudaGetSymbolAddress((void**)&QKV,  g_QKV);
    cudaGetSymbolAddress((void**)&Vth,  g_Vth);
    cudaGetSymbolAddress((void**)&Wall, g_Wall);
    cudaGetSymbolAddress((void**)&Sc,   g_Sc);
    cudaGetSymbolAddress((void**)&P,    g_P);

    cudaFuncSetAttribute(gemm_h<128, true>,  cudaFuncAttributeMaxDynamicSharedMemorySize, SMEM_128);
    cudaFuncSetAttribute(gemm_h<64, false>,  cudaFuncAttributeMaxDynamicSharedMemorySize, SMEM_64);

    const int M = BB * SS;                       // 8192
    const float scale = 1.f / sqrtf((float)UU);

    // 0) convert x to half; transpose+convert weights into packed Wall [3U, D]
    cvt_half<<<(BB * SS * DD / 4 + 255) / 256, 256>>>(x, Xh, BB * SS * DD / 4);
    dim3 tw(UU / 32, DD / 32, 1);
    transpose_f2h<<<tw, 256>>>(Wq, Wall + 0 * UU * DD, DD, UU);
    transpose_f2h<<<tw, 256>>>(Wk, Wall + 1 * UU * DD, DD, UU);
    transpose_f2h<<<tw, 256>>>(Wv, Wall + 2 * UU * DD, DD, UU);

    // 1) fused QKV projection (single launch, 1152 CTAs)
    dim3 gp(UQKV / 128, M / 128, 1);
    gemm_h<128, true><<<gp, 256, SMEM_128>>>(Xh, Wall, QKV,
                                             DD, DD, DD, UQKV, 0, 0, 0, 1.f);

    // 1b) transpose V per batch: QKV[:,1536:2304] -> Vth [U,S]
    dim3 tv(UU / 32, SS / 32, BB);
    transpose_h<<<tv, 256>>>(QKV + 2 * UU, Vth, UQKV, SS,
                             (long)SS * UQKV, (long)UU * SS);

    // 2) scores = scale * Q @ K^T (batched) — 64-M tiles vs quantization
    dim3 gs(SS / 128, SS / 64, BB);              // (16, 32, 4) = 2048 CTAs
    gemm_h<64, false><<<gs, 256, SMEM_64>>>(QKV + 0 * UU, QKV + 1 * UU, Sc,
                                            UU, UQKV, UQKV, SS,
                                            (long)SS * UQKV, (long)SS * UQKV,
                                            (long)SS * SS, scale);

    // 3) softmax rows: float scores -> half P
    softmax_rows<<<BB * SS, 256>>>(Sc, P);

    // 4) out = P @ V (batched) — 64-M tiles vs quantization
    dim3 ga(UU / 128, SS / 64, BB);              // (6, 32, 4) = 768 CTAs
    gemm_h<64, false><<<ga, 256, SMEM_64>>>(P, Vth, out,
                                            SS, SS, SS, UU,
                                            (long)SS * SS, (long)UU * SS,
                                            (long)SS * UU, 1.f);
}

// round 15
// speedup vs baseline: 1.0757x; 1.0757x over previous
#include <cuda_runtime.h>
#include <cuda_fp16.h>
#include <cstdint>
#include <math.h>

#define BB 4
#define SS 2048
#define DD 768
#define UU 768
#define UQKV (3 * UU)        // 2304

// ---------------- scratch (static __device__; allocs forbidden) --------------
__device__ __half g_Xh[BB * SS * DD];
__device__ __half g_QKV[(size_t)BB * SS * UQKV];   // packed [B*S, 3U]: Q | K | V
__device__ __half g_Vth[BB * UU * SS];
__device__ __half g_Wall[UQKV * DD];               // [3U, D]
__device__ float  g_Sc[(size_t)BB * SS * SS];
__device__ __half g_P[(size_t)BB * SS * SS];
__device__ float  g_Opart[2 * BB * SS * UU];       // split-K partials (fp32)

// ---------------- helpers ----------------------------------------------------
__device__ __forceinline__ void cp16(uint32_t s, const void* g) {
    asm volatile("cp.async.cg.shared.global [%0], [%1], 16;\n" :: "r"(s), "l"(g) : "memory");
}
__device__ __forceinline__ void cp_commit() {
    asm volatile("cp.async.commit_group;\n" ::: "memory");
}
template <int N>
__device__ __forceinline__ void cp_wait() {
    asm volatile("cp.async.wait_group %0;\n" :: "n"(N) : "memory");
}
__device__ __forceinline__ void mma_f16(float* d, const uint32_t* a, const uint32_t* b) {
    asm volatile("mma.sync.aligned.m16n8k16.row.col.f32.f16.f16.f32 "
                 "{%0,%1,%2,%3}, {%4,%5,%6,%7}, {%8,%9}, {%0,%1,%2,%3};"
                 : "+f"(d[0]), "+f"(d[1]), "+f"(d[2]), "+f"(d[3])
                 : "r"(a[0]), "r"(a[1]), "r"(a[2]), "r"(a[3]), "r"(b[0]), "r"(b[1]));
}
__device__ __forceinline__ void ldsm4(uint32_t& r0, uint32_t& r1, uint32_t& r2, uint32_t& r3,
                                      uint32_t addr) {
    asm volatile("ldmatrix.sync.aligned.m8n8.x4.shared.b16 {%0,%1,%2,%3}, [%4];"
                 : "=r"(r0), "=r"(r1), "=r"(r2), "=r"(r3) : "r"(addr));
}

// ---------------- fp16 warp-MMA GEMM: C = alpha * A * B^T --------------------
// CTA tile 128x128, K-chunk 64 halves, 8 warps (2M x 4N), warp tile 64x32.
// 3-stage cp.async pipeline, ONE __syncthreads per chunk.
// SPLITK: blockIdx.z = batch + NB*split (2 splits); A/B advance split*K in k,
// C goes to per-split partial buffer (sSplit element offset).
#define STRDH 72
#define TILE_HALFS (128 * STRDH)
#define SMEM_BYTES (3 * TILE_HALFS * 2 * 2)   // 110592

template <bool HALF_OUT, bool SPLITK>
__global__ __launch_bounds__(256, 2) void gemm_h(
    const __half* __restrict__ A, const __half* __restrict__ B, void* __restrict__ Cv,
    int K, int ldA, int ldB, int ldC,
    long sA, long sB, long sC, long sSplit, int nbatch, float alpha)
{
    extern __shared__ __half sm[];
    int zb = blockIdx.z, split = 0;
    if (SPLITK) { split = zb / nbatch; zb -= split * nbatch; }
    A += (long)zb * sA + (long)split * K;
    B += (long)zb * sB + (long)split * K;

    const int row0 = blockIdx.y * 128;
    const int col0 = blockIdx.x * 128;
    const int tid  = threadIdx.x;
    const int wid  = tid >> 5;
    const int lane = tid & 31;
    const int g    = lane >> 2;
    const int t    = lane & 3;
    const int wm   = wid & 1;
    const int wn   = wid >> 1;

    const uint32_t sA0 = (uint32_t)__cvta_generic_to_shared(sm);
    const uint32_t sB0 = (uint32_t)__cvta_generic_to_shared(sm + 3 * TILE_HALFS);

    const int aRow = wm * 64 + (lane & 15);
    const int aK8  = (lane >> 4) * 8;
    const int bRow = wn * 32 + ((lane >> 4) << 3) + (lane & 7);
    const int bK8  = ((lane >> 3) & 1) * 8;

    float acc[4][4][4];
#pragma unroll
    for (int i = 0; i < 4; i++)
#pragma unroll
        for (int j = 0; j < 4; j++)
#pragma unroll
            for (int r = 0; r < 4; r++) acc[i][j][r] = 0.f;

    const int KT = K / 64;

    auto load_tile = [&](int buf, int k0) {
        const uint32_t dA = sA0 + (uint32_t)(buf * TILE_HALFS * 2);
        const uint32_t dB = sB0 + (uint32_t)(buf * TILE_HALFS * 2);
#pragma unroll
        for (int i = 0; i < 4; i++) {
            int idx = tid + i * 256;
            int r   = idx >> 3;
            int c   = idx & 7;
            cp16(dA + (uint32_t)((r * STRDH + c * 8) * 2), A + (long)(row0 + r) * ldA + k0 + c * 8);
        }
#pragma unroll
        for (int i = 0; i < 4; i++) {
            int idx = tid + i * 256;
            int r   = idx >> 3;
            int c   = idx & 7;
            cp16(dB + (uint32_t)((r * STRDH + c * 8) * 2), B + (long)(col0 + r) * ldB + k0 + c * 8);
        }
        cp_commit();
    };

    load_tile(0, 0);
    load_tile(1, 64);

    int buf = 0;
    for (int kt = 0; kt < KT; kt++) {
        if (kt + 1 < KT) cp_wait<1>(); else cp_wait<0>();
        __syncthreads();
        if (kt + 2 < KT) {
            int wbuf = buf + 2; if (wbuf >= 3) wbuf -= 3;
            load_tile(wbuf, (kt + 2) * 64);
        }

        const uint32_t abase = sA0 + (uint32_t)(buf * TILE_HALFS * 2);
        const uint32_t bbase = sB0 + (uint32_t)(buf * TILE_HALFS * 2);

#pragma unroll
        for (int ks = 0; ks < 4; ks++) {
            const int kb = ks * 16;
            uint32_t af[4][4], bf[4][2];
#pragma unroll
            for (int mi = 0; mi < 4; mi++) {
                uint32_t addr = abase + (uint32_t)(((aRow + mi * 16) * STRDH + kb + aK8) * 2);
                ldsm4(af[mi][0], af[mi][1], af[mi][2], af[mi][3], addr);
            }
#pragma unroll
            for (int j = 0; j < 2; j++) {
                uint32_t addr = bbase + (uint32_t)(((bRow + j * 16) * STRDH + kb + bK8) * 2);
                ldsm4(bf[2 * j][0], bf[2 * j][1], bf[2 * j + 1][0], bf[2 * j + 1][1], addr);
            }
#pragma unroll
            for (int mi = 0; mi < 4; mi++)
#pragma unroll
                for (int ni = 0; ni < 4; ni++)
                    mma_f16(acc[mi][ni], af[mi], bf[ni]);
        }
        buf++; if (buf == 3) buf = 0;
    }

    // epilogue
#pragma unroll
    for (int mi = 0; mi < 4; mi++) {
        const int r0 = row0 + wm * 64 + mi * 16 + g;
#pragma unroll
        for (int ni = 0; ni < 4; ni++) {
            const int c = col0 + wn * 32 + ni * 8 + 2 * t;
            float v0 = acc[mi][ni][0] * alpha, v1 = acc[mi][ni][1] * alpha;
            float v2 = acc[mi][ni][2] * alpha, v3 = acc[mi][ni][3] * alpha;
            if (HALF_OUT) {
                __half* C = (__half*)Cv + (long)zb * sC;
                *(__half2*)(C + (long)r0 * ldC + c)       = __floats2half2_rn(v0, v1);
                *(__half2*)(C + (long)(r0 + 8) * ldC + c) = __floats2half2_rn(v2, v3);
            } else {
                float* C = (float*)Cv + (long)zb * sC + (SPLITK ? (long)split * sSplit : 0);
                *(float2*)(C + (long)r0 * ldC + c)       = make_float2(v0, v1);
                *(float2*)(C + (long)(r0 + 8) * ldC + c) = make_float2(v2, v3);
            }
        }
    }
}

// ---------------- split-K reduction: out = p0 + p1 (float4) ------------------
__global__ __launch_bounds__(256) void addk(const float* __restrict__ p,
                                            float* __restrict__ out, int n4, long sSplit4)
{
    int i = blockIdx.x * 256 + threadIdx.x;
    if (i < n4) {
        float4 a = ((const float4*)p)[i];
        float4 b = ((const float4*)p)[i + sSplit4];
        ((float4*)out)[i] = make_float4(a.x + b.x, a.y + b.y, a.z + b.z, a.w + b.w);
    }
}

// ---------------- fp32 -> fp16 copy ------------------------------------------
__global__ __launch_bounds__(256) void cvt_half(const float* __restrict__ in,
                                                __half* __restrict__ out, int n4)
{
    int i = blockIdx.x * 256 + threadIdx.x;
    if (i < n4) {
        float4 v = ((const float4*)in)[i];
        ((__half2*)out)[2 * i]     = __floats2half2_rn(v.x, v.y);
        ((__half2*)out)[2 * i + 1] = __floats2half2_rn(v.z, v.w);
    }
}

// ---------------- transpose float->half --------------------------------------
__global__ __launch_bounds__(256) void transpose_f2h(
    const float* __restrict__ in, __half* __restrict__ out, int R, int C)
{
    __shared__ float tbuf[32][33];
    const int c0 = blockIdx.x * 32, r0 = blockIdx.y * 32;
    const int tx = threadIdx.x & 31, ty = threadIdx.x >> 5;
#pragma unroll
    for (int i = 0; i < 32; i += 8)
        tbuf[ty + i][tx] = in[(long)(r0 + ty + i) * C + c0 + tx];
    __syncthreads();
#pragma unroll
    for (int i = 0; i < 32; i += 8)
        out[(long)(c0 + ty + i) * R + r0 + tx] = __float2half_rn(tbuf[tx][ty + i]);
}

// ---------------- transpose half->half with strides --------------------------
__global__ __launch_bounds__(256) void transpose_h(
    const __half* __restrict__ in, __half* __restrict__ out,
    int ldIn, int ldOut, long sIn, long sOut)
{
    __shared__ float tbuf[32][33];
    in  += (long)blockIdx.z * sIn;
    out += (long)blockIdx.z * sOut;
    const int c0 = blockIdx.x * 32, r0 = blockIdx.y * 32;
    const int tx = threadIdx.x & 31, ty = threadIdx.x >> 5;
#pragma unroll
    for (int i = 0; i < 32; i += 8)
        tbuf[ty + i][tx] = __half2float(in[(long)(r0 + ty + i) * ldIn + c0 + tx]);
    __syncthreads();
#pragma unroll
    for (int i = 0; i < 32; i += 8)
        out[(long)(c0 + ty + i) * ldOut + r0 + tx] = __float2half_rn(tbuf[tx][ty + i]);
}

// ---------------- row softmax over S=2048: float in, half out ----------------
__global__ __launch_bounds__(256) void softmax_rows(const float* __restrict__ scores,
                                                    __half* __restrict__ P)
{
    const float* row = scores + (long)blockIdx.x * SS;
    __half* prow = P + (long)blockIdx.x * SS;
    __shared__ float red[8];
    __shared__ float red2[8];
    const int t = threadIdx.x;
    const int lane = t & 31, warp = t >> 5;

    float v[8];
    float m = -INFINITY;
#pragma unroll
    for (int i = 0; i < 8; i++) { v[i] = row[t + i * 256]; m = fmaxf(m, v[i]); }
#pragma unroll
    for (int off = 16; off > 0; off >>= 1)
        m = fmaxf(m, __shfl_xor_sync(0xFFFFFFFFu, m, off));
    if (lane == 0) red[warp] = m;
    __syncthreads();
#pragma unroll
    for (int w = 0; w < 8; w++) m = fmaxf(m, red[w]);

    float sum = 0.f;
#pragma unroll
    for (int i = 0; i < 8; i++) { v[i] = __expf(v[i] - m); sum += v[i]; }
#pragma unroll
    for (int off = 16; off > 0; off >>= 1)
        sum += __shfl_xor_sync(0xFFFFFFFFu, sum, off);
    if (lane == 0) red2[warp] = sum;
    __syncthreads();
    sum = 0.f;
#pragma unroll
    for (int w = 0; w < 8; w++) sum += red2[w];

    float inv = 1.f / sum;
#pragma unroll
    for (int i = 0; i < 8; i++) prow[t + i * 256] = __float2half_rn(v[i] * inv);
}

// ---------------------------------------------------------------------------
extern "C" void kernel_launch(void* const* d_in, const int* in_sizes, int n_in,
                              void* d_out, int out_size)
{
    (void)in_sizes; (void)n_in; (void)out_size;
    const float* x  = (const float*)d_in[0];
    const float* Wq = (const float*)d_in[1];
    const float* Wk = (const float*)d_in[2];
    const float* Wv = (const float*)d_in[3];
    float* out = (float*)d_out;

    __half *Xh, *QKV, *Vth, *Wall, *P;
    float *Sc, *Op;
    cudaGetSymbolAddress((void**)&Xh,   g_Xh);
    cudaGetSymbolAddress((void**)&QKV,  g_QKV);
    cudaGetSymbolAddress((void**)&Vth,  g_Vth);
    cudaGetSymbolAddress((void**)&Wall, g_Wall);
    cudaGetSymbolAddress((void**)&Sc,   g_Sc);
    cudaGetSymbolAddress((void**)&P,    g_P);
    cudaGetSymbolAddress((void**)&Op,   g_Opart);

    cudaFuncSetAttribute((const void*)gemm_h<true, false>,
                         cudaFuncAttributeMaxDynamicSharedMemorySize, SMEM_BYTES);
    cudaFuncSetAttribute((const void*)gemm_h<false, false>,
                         cudaFuncAttributeMaxDynamicSharedMemorySize, SMEM_BYTES);
    cudaFuncSetAttribute((const void*)gemm_h<false, true>,
                         cudaFuncAttributeMaxDynamicSharedMemorySize, SMEM_BYTES);

    const int M = BB * SS;                       // 8192
    const float scale = 1.f / sqrtf((float)UU);
    const long sOut = (long)SS * UU;             // per-batch out stride
    const long sSplit = (long)BB * SS * UU;      // per-split partial stride

    // 0) convert x to half; transpose+convert weights into packed Wall [3U, D]
    cvt_half<<<(BB * SS * DD / 4 + 255) / 256, 256>>>(x, Xh, BB * SS * DD / 4);
    dim3 tw(UU / 32, DD / 32, 1);
    transpose_f2h<<<tw, 256>>>(Wq, Wall + 0 * UU * DD, DD, UU);
    transpose_f2h<<<tw, 256>>>(Wk, Wall + 1 * UU * DD, DD, UU);
    transpose_f2h<<<tw, 256>>>(Wv, Wall + 2 * UU * DD, DD, UU);

    // 1) fused QKV projection (single launch, 1152 CTAs)
    dim3 gp(UQKV / 128, M / 128, 1);
    gemm_h<true, false><<<gp, 256, SMEM_BYTES>>>(Xh, Wall, QKV,
                                                 DD, DD, DD, UQKV,
                                                 0, 0, 0, 0, 1, 1.f);

    // 1b) transpose V per batch: QKV[:,1536:2304] -> Vth [U,S]
    dim3 tv(UU / 32, SS / 32, BB);
    transpose_h<<<tv, 256>>>(QKV + 2 * UU, Vth, UQKV, SS,
                             (long)SS * UQKV, (long)UU * SS);

    // 2) scores = scale * Q @ K^T (batched) -> float
    dim3 gs(SS / 128, SS / 128, BB);             // 1024 CTAs
    gemm_h<false, false><<<gs, 256, SMEM_BYTES>>>(QKV + 0 * UU, QKV + 1 * UU, Sc,
                                                  UU, UQKV, UQKV, SS,
                                                  (long)SS * UQKV, (long)SS * UQKV,
                                                  (long)SS * SS, 0, 1, scale);

    // 3) softmax rows: float scores -> half P
    softmax_rows<<<BB * SS, 256>>>(Sc, P);

    // 4) out = P @ V, split-K=2 over K=2048 -> fp32 partials (768 CTAs)
    dim3 ga(UU / 128, SS / 128, 2 * BB);         // (6, 16, 8)
    gemm_h<false, true><<<ga, 256, SMEM_BYTES>>>(P, Vth, Op,
                                                 SS / 2, SS, SS, UU,
                                                 (long)SS * SS, (long)UU * SS,
                                                 sOut, sSplit, BB, 1.f);

    // 4b) reduce partials into out
    int n4 = BB * SS * UU / 4;
    addk<<<(n4 + 255) / 256, 256>>>(Op, out, n4, sSplit / 4);
}

// round 16
// speedup vs baseline: 1.1325x; 1.0528x over previous
#include <cuda_runtime.h>
#include <cuda_fp16.h>
#include <cstdint>
#include <math.h>

#define BB 4
#define SS 2048
#define DD 768
#define UU 768
#define UQKV (3 * UU)        // 2304

// ---------------- scratch (static __device__; allocs forbidden) --------------
__device__ __half g_Xh[BB * SS * DD];
__device__ __half g_QKV[(size_t)BB * SS * UQKV];   // packed [B*S, 3U]: Q | K | (V unused)
__device__ __half g_Vth[BB * UU * SS];             // V^T per batch [U, S]
__device__ __half g_Wall[UQKV * DD];               // [3U, D]
__device__ float  g_Sc[(size_t)BB * SS * SS];
__device__ __half g_P[(size_t)BB * SS * SS];

// ---------------- helpers ----------------------------------------------------
__device__ __forceinline__ void cp16(uint32_t s, const void* g) {
    asm volatile("cp.async.cg.shared.global [%0], [%1], 16;\n" :: "r"(s), "l"(g) : "memory");
}
__device__ __forceinline__ void cp_commit() {
    asm volatile("cp.async.commit_group;\n" ::: "memory");
}
template <int N>
__device__ __forceinline__ void cp_wait() {
    asm volatile("cp.async.wait_group %0;\n" :: "n"(N) : "memory");
}
__device__ __forceinline__ void mma_f16(float* d, const uint32_t* a, const uint32_t* b) {
    asm volatile("mma.sync.aligned.m16n8k16.row.col.f32.f16.f16.f32 "
                 "{%0,%1,%2,%3}, {%4,%5,%6,%7}, {%8,%9}, {%0,%1,%2,%3};"
                 : "+f"(d[0]), "+f"(d[1]), "+f"(d[2]), "+f"(d[3])
                 : "r"(a[0]), "r"(a[1]), "r"(a[2]), "r"(a[3]), "r"(b[0]), "r"(b[1]));
}
__device__ __forceinline__ void ldsm4(uint32_t& r0, uint32_t& r1, uint32_t& r2, uint32_t& r3,
                                      uint32_t addr) {
    asm volatile("ldmatrix.sync.aligned.m8n8.x4.shared.b16 {%0,%1,%2,%3}, [%4];"
                 : "=r"(r0), "=r"(r1), "=r"(r2), "=r"(r3) : "r"(addr));
}

// ---------------- fp16 warp-MMA GEMM: C = alpha * A * B^T --------------------
// CTA tile 128x128, K-chunk 64 halves, 8 warps (2M x 4N), warp tile 64x32.
// 3-stage cp.async pipeline, ONE __syncthreads per chunk.
// VT_EPI: CTAs with col0 >= 1536 write their tile TRANSPOSED to Vt (per-batch
// [U, S]) via an smem staging transpose, instead of writing C.
#define STRDH 72
#define TILE_HALFS (128 * STRDH)
#define SMEM_BYTES (3 * TILE_HALFS * 2 * 2)   // 110592

template <bool HALF_OUT, bool VT_EPI>
__global__ __launch_bounds__(256, 2) void gemm_h(
    const __half* __restrict__ A, const __half* __restrict__ B, void* __restrict__ Cv,
    __half* __restrict__ Vt,
    int K, int ldA, int ldB, int ldC,
    long sA, long sB, long sC, float alpha)
{
    extern __shared__ __half sm[];
    A += (long)blockIdx.z * sA;
    B += (long)blockIdx.z * sB;

    const int row0 = blockIdx.y * 128;
    const int col0 = blockIdx.x * 128;
    const int tid  = threadIdx.x;
    const int wid  = tid >> 5;
    const int lane = tid & 31;
    const int g    = lane >> 2;
    const int t    = lane & 3;
    const int wm   = wid & 1;
    const int wn   = wid >> 1;

    const uint32_t sA0 = (uint32_t)__cvta_generic_to_shared(sm);
    const uint32_t sB0 = (uint32_t)__cvta_generic_to_shared(sm + 3 * TILE_HALFS);

    const int aRow = wm * 64 + (lane & 15);
    const int aK8  = (lane >> 4) * 8;
    const int bRow = wn * 32 + ((lane >> 4) << 3) + (lane & 7);
    const int bK8  = ((lane >> 3) & 1) * 8;

    float acc[4][4][4];
#pragma unroll
    for (int i = 0; i < 4; i++)
#pragma unroll
        for (int j = 0; j < 4; j++)
#pragma unroll
            for (int r = 0; r < 4; r++) acc[i][j][r] = 0.f;

    const int KT = K / 64;

    auto load_tile = [&](int buf, int k0) {
        const uint32_t dA = sA0 + (uint32_t)(buf * TILE_HALFS * 2);
        const uint32_t dB = sB0 + (uint32_t)(buf * TILE_HALFS * 2);
#pragma unroll
        for (int i = 0; i < 4; i++) {
            int idx = tid + i * 256;
            int r   = idx >> 3;
            int c   = idx & 7;
            cp16(dA + (uint32_t)((r * STRDH + c * 8) * 2), A + (long)(row0 + r) * ldA + k0 + c * 8);
        }
#pragma unroll
        for (int i = 0; i < 4; i++) {
            int idx = tid + i * 256;
            int r   = idx >> 3;
            int c   = idx & 7;
            cp16(dB + (uint32_t)((r * STRDH + c * 8) * 2), B + (long)(col0 + r) * ldB + k0 + c * 8);
        }
        cp_commit();
    };

    load_tile(0, 0);
    load_tile(1, 64);

    int buf = 0;
    for (int kt = 0; kt < KT; kt++) {
        if (kt + 1 < KT) cp_wait<1>(); else cp_wait<0>();
        __syncthreads();
        if (kt + 2 < KT) {
            int wbuf = buf + 2; if (wbuf >= 3) wbuf -= 3;
            load_tile(wbuf, (kt + 2) * 64);
        }

        const uint32_t abase = sA0 + (uint32_t)(buf * TILE_HALFS * 2);
        const uint32_t bbase = sB0 + (uint32_t)(buf * TILE_HALFS * 2);

#pragma unroll
        for (int ks = 0; ks < 4; ks++) {
            const int kb = ks * 16;
            uint32_t af[4][4], bf[4][2];
#pragma unroll
            for (int mi = 0; mi < 4; mi++) {
                uint32_t addr = abase + (uint32_t)(((aRow + mi * 16) * STRDH + kb + aK8) * 2);
                ldsm4(af[mi][0], af[mi][1], af[mi][2], af[mi][3], addr);
            }
#pragma unroll
            for (int j = 0; j < 2; j++) {
                uint32_t addr = bbase + (uint32_t)(((bRow + j * 16) * STRDH + kb + bK8) * 2);
                ldsm4(bf[2 * j][0], bf[2 * j][1], bf[2 * j + 1][0], bf[2 * j + 1][1], addr);
            }
#pragma unroll
            for (int mi = 0; mi < 4; mi++)
#pragma unroll
                for (int ni = 0; ni < 4; ni++)
                    mma_f16(acc[mi][ni], af[mi], bf[ni]);
        }
        buf++; if (buf == 3) buf = 0;
    }

    // ---- epilogue ----
    if (VT_EPI && col0 >= 3 * UU - UU) {   // col0 >= 1536: V segment
        // stage tile into smem (half), then write transposed, coalesced
        __half (*st)[136] = (__half(*)[136])sm;
        __syncthreads();                    // all warps past last compute reads
#pragma unroll
        for (int mi = 0; mi < 4; mi++) {
            const int r = wm * 64 + mi * 16 + g;
#pragma unroll
            for (int ni = 0; ni < 4; ni++) {
                const int c = wn * 32 + ni * 8 + 2 * t;
                *(__half2*)&st[r][c]     = __floats2half2_rn(acc[mi][ni][0] * alpha,
                                                             acc[mi][ni][1] * alpha);
                *(__half2*)&st[r + 8][c] = __floats2half2_rn(acc[mi][ni][2] * alpha,
                                                             acc[mi][ni][3] * alpha);
            }
        }
        __syncthreads();
        const int bb   = row0 >> 11;        // 2048 rows per batch
        const int srow = row0 & 2047;
        __half* Vb = Vt + (long)bb * UU * SS + (long)(col0 - 1536) * SS + srow;
#pragma unroll
        for (int i = 0; i < 32; i++) {
            int idx = tid + i * 256;        // 0..8191
            int c   = idx >> 6;             // 0..127 (column of tile)
            int rh  = idx & 63;             // half2 row index
            __half2 hv = __halves2half2(st[2 * rh][c], st[2 * rh + 1][c]);
            *(__half2*)(Vb + (long)c * SS + 2 * rh) = hv;
        }
        return;
    }
#pragma unroll
    for (int mi = 0; mi < 4; mi++) {
        const int r0 = row0 + wm * 64 + mi * 16 + g;
#pragma unroll
        for (int ni = 0; ni < 4; ni++) {
            const int c = col0 + wn * 32 + ni * 8 + 2 * t;
            float v0 = acc[mi][ni][0] * alpha, v1 = acc[mi][ni][1] * alpha;
            float v2 = acc[mi][ni][2] * alpha, v3 = acc[mi][ni][3] * alpha;
            if (HALF_OUT) {
                __half* C = (__half*)Cv + (long)blockIdx.z * sC;
                *(__half2*)(C + (long)r0 * ldC + c)       = __floats2half2_rn(v0, v1);
                *(__half2*)(C + (long)(r0 + 8) * ldC + c) = __floats2half2_rn(v2, v3);
            } else {
                float* C = (float*)Cv + (long)blockIdx.z * sC;
                *(float2*)(C + (long)r0 * ldC + c)       = make_float2(v0, v1);
                *(float2*)(C + (long)(r0 + 8) * ldC + c) = make_float2(v2, v3);
            }
        }
    }
}

// ---------------- fp32 -> fp16 copy ------------------------------------------
__global__ __launch_bounds__(256) void cvt_half(const float* __restrict__ in,
                                                __half* __restrict__ out, int n4)
{
    int i = blockIdx.x * 256 + threadIdx.x;
    if (i < n4) {
        float4 v = ((const float4*)in)[i];
        ((__half2*)out)[2 * i]     = __floats2half2_rn(v.x, v.y);
        ((__half2*)out)[2 * i + 1] = __floats2half2_rn(v.z, v.w);
    }
}

// ---------------- merged weight transpose: 3 weights in one launch -----------
// z selects Wq/Wk/Wv; writes W^T into Wall segment z. in [D,U] -> out [U,D].
__global__ __launch_bounds__(256) void transpose_w3(
    const float* __restrict__ Wq, const float* __restrict__ Wk,
    const float* __restrict__ Wv, __half* __restrict__ outBase)
{
    __shared__ float tbuf[32][33];
    const float* in = (blockIdx.z == 0) ? Wq : (blockIdx.z == 1) ? Wk : Wv;
    __half* out = outBase + (size_t)blockIdx.z * UU * DD;
    const int c0 = blockIdx.x * 32, r0 = blockIdx.y * 32;
    const int tx = threadIdx.x & 31, ty = threadIdx.x >> 5;
#pragma unroll
    for (int i = 0; i < 32; i += 8)
        tbuf[ty + i][tx] = in[(long)(r0 + ty + i) * UU + c0 + tx];
    __syncthreads();
#pragma unroll
    for (int i = 0; i < 32; i += 8)
        out[(long)(c0 + ty + i) * DD + r0 + tx] = __float2half_rn(tbuf[tx][ty + i]);
}

// ---------------- row softmax over S=2048: float in, half out ----------------
__global__ __launch_bounds__(256) void softmax_rows(const float* __restrict__ scores,
                                                    __half* __restrict__ P)
{
    const float* row = scores + (long)blockIdx.x * SS;
    __half* prow = P + (long)blockIdx.x * SS;
    __shared__ float red[8];
    __shared__ float red2[8];
    const int t = threadIdx.x;
    const int lane = t & 31, warp = t >> 5;

    float v[8];
    float m = -INFINITY;
#pragma unroll
    for (int i = 0; i < 8; i++) { v[i] = row[t + i * 256]; m = fmaxf(m, v[i]); }
#pragma unroll
    for (int off = 16; off > 0; off >>= 1)
        m = fmaxf(m, __shfl_xor_sync(0xFFFFFFFFu, m, off));
    if (lane == 0) red[warp] = m;
    __syncthreads();
#pragma unroll
    for (int w = 0; w < 8; w++) m = fmaxf(m, red[w]);

    float sum = 0.f;
#pragma unroll
    for (int i = 0; i < 8; i++) { v[i] = __expf(v[i] - m); sum += v[i]; }
#pragma unroll
    for (int off = 16; off > 0; off >>= 1)
        sum += __shfl_xor_sync(0xFFFFFFFFu, sum, off);
    if (lane == 0) red2[warp] = sum;
    __syncthreads();
    sum = 0.f;
#pragma unroll
    for (int w = 0; w < 8; w++) sum += red2[w];

    float inv = 1.f / sum;
#pragma unroll
    for (int i = 0; i < 8; i++) prow[t + i * 256] = __float2half_rn(v[i] * inv);
}

// ---------------------------------------------------------------------------
extern "C" void kernel_launch(void* const* d_in, const int* in_sizes, int n_in,
                              void* d_out, int out_size)
{
    (void)in_sizes; (void)n_in; (void)out_size;
    const float* x  = (const float*)d_in[0];
    const float* Wq = (const float*)d_in[1];
    const float* Wk = (const float*)d_in[2];
    const float* Wv = (const float*)d_in[3];
    float* out = (float*)d_out;

    __half *Xh, *QKV, *Vth, *Wall, *P;
    float *Sc;
    cudaGetSymbolAddress((void**)&Xh,   g_Xh);
    cudaGetSymbolAddress((void**)&QKV,  g_QKV);
    cudaGetSymbolAddress((void**)&Vth,  g_Vth);
    cudaGetSymbolAddress((void**)&Wall, g_Wall);
    cudaGetSymbolAddress((void**)&Sc,   g_Sc);
    cudaGetSymbolAddress((void**)&P,    g_P);

    cudaFuncSetAttribute((const void*)gemm_h<true, true>,
                         cudaFuncAttributeMaxDynamicSharedMemorySize, SMEM_BYTES);
    cudaFuncSetAttribute((const void*)gemm_h<false, false>,
                         cudaFuncAttributeMaxDynamicSharedMemorySize, SMEM_BYTES);

    const int M = BB * SS;                       // 8192
    const float scale = 1.f / sqrtf((float)UU);

    // 0) convert x to half; one merged transpose launch for all 3 weights
    cvt_half<<<(BB * SS * DD / 4 + 255) / 256, 256>>>(x, Xh, BB * SS * DD / 4);
    dim3 tw(UU / 32, DD / 32, 3);
    transpose_w3<<<tw, 256>>>(Wq, Wk, Wv, Wall);

    // 1) fused QKV projection; V tiles stream transposed into Vth in-epilogue
    dim3 gp(UQKV / 128, M / 128, 1);             // 1152 CTAs
    gemm_h<true, true><<<gp, 256, SMEM_BYTES>>>(Xh, Wall, QKV, Vth,
                                                DD, DD, DD, UQKV, 0, 0, 0, 1.f);

    // 2) scores = scale * Q @ K^T (batched) -> float
    dim3 gs(SS / 128, SS / 128, BB);             // 1024 CTAs
    gemm_h<false, false><<<gs, 256, SMEM_BYTES>>>(QKV + 0 * UU, QKV + 1 * UU, Sc, nullptr,
                                                  UU, UQKV, UQKV, SS,
                                                  (long)SS * UQKV, (long)SS * UQKV,
                                                  (long)SS * SS, scale);

    // 3) softmax rows: float scores -> half P
    softmax_rows<<<BB * SS, 256>>>(Sc, P);

    // 4) out = P @ V (batched) -> float
    dim3 ga(UU / 128, SS / 128, BB);             // 384 CTAs
    gemm_h<false, false><<<ga, 256, SMEM_BYTES>>>(P, Vth, out, nullptr,
                                                  SS, SS, SS, UU,
                                                  (long)SS * SS, (long)UU * SS,
                                                  (long)SS * UU, 1.f);
}